// round 17
// baseline (speedup 1.0000x reference)
#include <cuda_runtime.h>
#include <cstdint>

// Problem-fixed maxima (N=100000, E=3200000 per reference setup_inputs).
#define MAXN 100000
#define MAXE 3200000
#define NTHR 256

// Scratch (allocation-free contract: __device__ globals; zero-init at load).
__device__ int g_cnt[MAXN];                        // in-degree (excl self-loop); reset each call
__device__ __align__(16) float g_xs[MAXN * 4];     // x * dinv  (source-scaled payload)
__device__ __align__(16) float g_accx[MAXN * 4];   // layer-1 accumulator (pre dst-scale)
__device__ __align__(16) float g_t2s[MAXN * 4];    // t2 * dinv (source-scaled payload)
__device__ __align__(16) float g_acc2[MAXN * 4];   // layer-2 accumulator (pre dst-scale)
__device__ float g_dinv[MAXN];                     // rsqrt(deg)

// Software grid barrier state (self-resetting; gen is monotonic across calls).
__device__ unsigned g_bar_arrive;                  // = 0 between barriers
__device__ unsigned g_bar_gen;

__device__ __forceinline__ void red_add_v4(float* addr, float a, float b, float c, float d) {
    asm volatile("red.global.add.v4.f32 [%0], {%1, %2, %3, %4};"
                 :: "l"(addr), "f"(a), "f"(b), "f"(c), "f"(d) : "memory");
}

// Grid-wide barrier. Requires all blocks co-resident (grid sized to occupancy).
__device__ __forceinline__ void grid_barrier(unsigned nblocks) {
    __syncthreads();
    if (threadIdx.x == 0) {
        __threadfence();                              // publish this block's phase writes
        unsigned gen = *(volatile unsigned*)&g_bar_gen;
        if (atomicAdd(&g_bar_arrive, 1u) == nblocks - 1u) {
            g_bar_arrive = 0;
            __threadfence();
            atomicExch(&g_bar_gen, gen + 1u);         // release
        } else {
            while (*(volatile unsigned*)&g_bar_gen == gen) { __nanosleep(40); }
            __threadfence();                          // acquire
        }
    }
    __syncthreads();
}

__global__ void __launch_bounds__(NTHR, 4)
k_mega(const float* __restrict__ x, const int* __restrict__ edge_index,
       const float* __restrict__ W1, const float* __restrict__ b1,
       const float* __restrict__ W2, const float* __restrict__ b2,
       float* __restrict__ out, int n, int E, unsigned nblocks) {
    __shared__ float sW1[96];   // W1 [3, 32] row-major
    __shared__ float sb1[32];
    __shared__ float sW2[96];   // W2 [32, 3] row-major
    __shared__ float sb2[3];
    if (threadIdx.x < 96) sW1[threadIdx.x] = W1[threadIdx.x];
    if (threadIdx.x < 32) sb1[threadIdx.x] = b1[threadIdx.x];
    if (threadIdx.x >= 128 && threadIdx.x < 224) sW2[threadIdx.x - 128] = W2[threadIdx.x - 128];
    if (threadIdx.x >= 224 && threadIdx.x < 227) sb2[threadIdx.x - 224] = b2[threadIdx.x - 224];
    __syncthreads();

    const unsigned tid0 = blockIdx.x * NTHR + threadIdx.x;
    const unsigned stride = nblocks * NTHR;
    const int G4 = (E + 3) / 4;                      // int4 edge groups
    const int* srcp = edge_index;
    const int* dstp = edge_index + E;

    // ── Phase 1: in-degree histogram (4 edges/thread via int4) ──
    for (unsigned g = tid0; g < (unsigned)G4; g += stride) {
        int e0 = g * 4;
        if (e0 + 3 < E) {
            int4 d4 = *reinterpret_cast<const int4*>(dstp + e0);
            atomicAdd(&g_cnt[d4.x], 1);
            atomicAdd(&g_cnt[d4.y], 1);
            atomicAdd(&g_cnt[d4.z], 1);
            atomicAdd(&g_cnt[d4.w], 1);
        } else {
            for (int e = e0; e < E; e++) atomicAdd(&g_cnt[dstp[e]], 1);
        }
    }
    grid_barrier(nblocks);

    // ── Phase 2: dinv = rsqrt(deg+1); xs = x*dinv; seed accx (self-loop); reset cnt ──
    for (unsigned i = tid0; i < (unsigned)n; i += stride) {
        int c = g_cnt[i];
        g_cnt[i] = 0;                                // restore zero for next call
        float di = rsqrtf((float)(c + 1));
        g_dinv[i] = di;
        float4 p = make_float4(x[i * 3 + 0] * di, x[i * 3 + 1] * di, x[i * 3 + 2] * di, 0.f);
        reinterpret_cast<float4*>(g_xs)[i] = p;
        reinterpret_cast<float4*>(g_accx)[i] = p;
    }
    grid_barrier(nblocks);

    // ── Phase 3: layer-1 weightless copy-scatter (4 edges/thread) ──
    {
        const float4* xs = reinterpret_cast<const float4*>(g_xs);
        for (unsigned g = tid0; g < (unsigned)G4; g += stride) {
            int e0 = g * 4;
            if (e0 + 3 < E) {
                int4 s4 = *reinterpret_cast<const int4*>(srcp + e0);
                int4 d4 = *reinterpret_cast<const int4*>(dstp + e0);
                float4 v0 = xs[s4.x];
                float4 v1 = xs[s4.y];
                float4 v2 = xs[s4.z];
                float4 v3 = xs[s4.w];
                red_add_v4(&g_accx[d4.x * 4], v0.x, v0.y, v0.z, 0.f);
                red_add_v4(&g_accx[d4.y * 4], v1.x, v1.y, v1.z, 0.f);
                red_add_v4(&g_accx[d4.z * 4], v2.x, v2.y, v2.z, 0.f);
                red_add_v4(&g_accx[d4.w * 4], v3.x, v3.y, v3.z, 0.f);
            } else {
                for (int e = e0; e < E; e++) {
                    float4 v = xs[srcp[e]];
                    red_add_v4(&g_accx[dstp[e] * 4], v.x, v.y, v.z, 0.f);
                }
            }
        }
    }
    grid_barrier(nblocks);

    // ── Phase 4: agg1 = accx*dinv -> h = relu(agg1@W1+b1) -> t2 = h@W2;
    //            payload t2s = t2*dinv; seed acc2 (self-loop) ──
    for (unsigned i = tid0; i < (unsigned)n; i += stride) {
        float di = g_dinv[i];
        float4 a = reinterpret_cast<const float4*>(g_accx)[i];
        a.x *= di; a.y *= di; a.z *= di;
        float c0 = 0.f, c1 = 0.f, c2 = 0.f;
#pragma unroll
        for (int j = 0; j < 32; j++) {
            float h = fmaxf(a.x * sW1[j] + a.y * sW1[32 + j] + a.z * sW1[64 + j] + sb1[j], 0.f);
            c0 += h * sW2[j * 3 + 0];
            c1 += h * sW2[j * 3 + 1];
            c2 += h * sW2[j * 3 + 2];
        }
        float4 p = make_float4(c0 * di, c1 * di, c2 * di, 0.f);
        reinterpret_cast<float4*>(g_t2s)[i] = p;
        reinterpret_cast<float4*>(g_acc2)[i] = p;
    }
    grid_barrier(nblocks);

    // ── Phase 5: layer-2 weightless copy-scatter (4 edges/thread) ──
    {
        const float4* ts = reinterpret_cast<const float4*>(g_t2s);
        for (unsigned g = tid0; g < (unsigned)G4; g += stride) {
            int e0 = g * 4;
            if (e0 + 3 < E) {
                int4 s4 = *reinterpret_cast<const int4*>(srcp + e0);
                int4 d4 = *reinterpret_cast<const int4*>(dstp + e0);
                float4 v0 = ts[s4.x];
                float4 v1 = ts[s4.y];
                float4 v2 = ts[s4.z];
                float4 v3 = ts[s4.w];
                red_add_v4(&g_acc2[d4.x * 4], v0.x, v0.y, v0.z, 0.f);
                red_add_v4(&g_acc2[d4.y * 4], v1.x, v1.y, v1.z, 0.f);
                red_add_v4(&g_acc2[d4.z * 4], v2.x, v2.y, v2.z, 0.f);
                red_add_v4(&g_acc2[d4.w * 4], v3.x, v3.y, v3.z, 0.f);
            } else {
                for (int e = e0; e < E; e++) {
                    float4 v = ts[srcp[e]];
                    red_add_v4(&g_acc2[dstp[e] * 4], v.x, v.y, v.z, 0.f);
                }
            }
        }
    }
    grid_barrier(nblocks);

    // ── Phase 6: out = acc2 * dinv + b2 ──
    for (unsigned i = tid0; i < (unsigned)n; i += stride) {
        float di = g_dinv[i];
        float4 a = reinterpret_cast<const float4*>(g_acc2)[i];
        out[i * 3 + 0] = a.x * di + sb2[0];
        out[i * 3 + 1] = a.y * di + sb2[1];
        out[i * 3 + 2] = a.z * di + sb2[2];
    }
}

extern "C" void kernel_launch(void* const* d_in, const int* in_sizes, int n_in,
                              void* d_out, int out_size) {
    const float* x = (const float*)d_in[0];
    const int* edge_index = (const int*)d_in[1];  // int32 (JAX x64 disabled)
    const float* W1 = (const float*)d_in[2];
    const float* b1 = (const float*)d_in[3];
    const float* W2 = (const float*)d_in[4];
    const float* b2 = (const float*)d_in[5];
    float* out = (float*)d_out;

    int n = in_sizes[0] / 3;
    int E = in_sizes[1] / 2;

    // Co-residency-safe grid: SMs x occupancy (launch_bounds guarantees >= 4).
    static int s_blocks = 0;  // deterministic: device properties are fixed
    if (s_blocks == 0) {
        int dev = 0, sms = 0, occ = 0;
        cudaGetDevice(&dev);
        cudaDeviceGetAttribute(&sms, cudaDevAttrMultiProcessorCount, dev);
        cudaOccupancyMaxActiveBlocksPerMultiprocessor(&occ, k_mega, NTHR, 0);
        if (occ < 1) occ = 1;
        if (occ > 8) occ = 8;
        s_blocks = sms * occ;
    }
    unsigned nblocks = (unsigned)s_blocks;

    k_mega<<<nblocks, NTHR>>>(x, edge_index, W1, b1, W2, b2, out, n, E, nblocks);
}